// round 1
// baseline (speedup 1.0000x reference)
#include <cuda_runtime.h>
#include <cuda_bf16.h>
#include <mma.h>
#include <cstddef>

using namespace nvcuda;

#define Bv    8
#define Tv    2048
#define Cv    1024
#define Hv    16
#define Nv    64
#define FFNv  3584
#define TOK   (Bv*Tv)            // 16384 tokens
#define HSDv  8.0f
#define EPSv  1e-5f

// ---------------- scratch (static device arrays; no allocations) ----------------
__device__ float g_x  [(size_t)TOK*Cv];   // residual stream
__device__ float g_xn [(size_t)TOK*Cv];   // layernorm output
__device__ float g_b0 [(size_t)TOK*Cv];   // xk   -> later wkv y
__device__ float g_b1 [(size_t)TOK*Cv];   // xv   -> later gy
__device__ float g_b2 [(size_t)TOK*Cv];   // xr   -> later ffn xr
__device__ float g_b3 [(size_t)TOK*Cv];   // xg   -> later ffn xk
__device__ float g_b4 [(size_t)TOK*Cv];   // r    -> later sigmoid(ffn r)
__device__ float g_b5 [(size_t)TOK*Cv];   // k    -> later kv
__device__ float g_b6 [(size_t)TOK*Cv];   // v
__device__ float g_b7 [(size_t)TOK*Cv];   // silu(g)
__device__ float g_big[(size_t)TOK*FFNv]; // ffn hidden (relu^2)

// ---------------- helpers ----------------
__device__ __forceinline__ float tf32r(float x) {
    float y; asm("cvt.rna.tf32.f32 %0, %1;" : "=f"(y) : "f"(x)); return y;
}

// block-wide sum of (s, ss) for blockDim.x == 256
__device__ __forceinline__ void block_reduce2(float& s, float& ss) {
    __shared__ float red[64];
    __syncthreads();  // protect reuse across consecutive calls
    #pragma unroll
    for (int o = 16; o; o >>= 1) {
        s  += __shfl_xor_sync(0xffffffffu, s,  o);
        ss += __shfl_xor_sync(0xffffffffu, ss, o);
    }
    int lane = threadIdx.x & 31, w = threadIdx.x >> 5;
    if (lane == 0) { red[w] = s; red[32 + w] = ss; }
    __syncthreads();
    if (w == 0) {
        float a = (lane < 8) ? red[lane]      : 0.f;
        float c = (lane < 8) ? red[32 + lane] : 0.f;
        #pragma unroll
        for (int o = 4; o; o >>= 1) {
            a += __shfl_xor_sync(0xffffffffu, a, o);
            c += __shfl_xor_sync(0xffffffffu, c, o);
        }
        if (lane == 0) { red[0] = a; red[32] = c; }
    }
    __syncthreads();
    s = red[0]; ss = red[32];
}

// ---------------- LN kernels ----------------
// fused ln0 then ln1: writes g_x (post-ln0) and g_xn (post-ln1)
__global__ void __launch_bounds__(256) ln0_ln1_kernel(
    const float* __restrict__ x,
    const float* __restrict__ w0, const float* __restrict__ b0,
    const float* __restrict__ w1, const float* __restrict__ b1)
{
    size_t tok = blockIdx.x;
    int t = threadIdx.x;
    float4 v = ((const float4*)(x + tok*Cv))[t];
    float s  = v.x + v.y + v.z + v.w;
    float ss = v.x*v.x + v.y*v.y + v.z*v.z + v.w*v.w;
    block_reduce2(s, ss);
    float mu  = s * (1.f/Cv);
    float inv = rsqrtf(ss * (1.f/Cv) - mu*mu + EPSv);
    float4 W = ((const float4*)w0)[t], Bb = ((const float4*)b0)[t];
    float4 h;
    h.x = (v.x-mu)*inv*W.x + Bb.x;  h.y = (v.y-mu)*inv*W.y + Bb.y;
    h.z = (v.z-mu)*inv*W.z + Bb.z;  h.w = (v.w-mu)*inv*W.w + Bb.w;
    ((float4*)(g_x + tok*Cv))[t] = h;
    // second LN on h
    s  = h.x + h.y + h.z + h.w;
    ss = h.x*h.x + h.y*h.y + h.z*h.z + h.w*h.w;
    block_reduce2(s, ss);
    mu  = s * (1.f/Cv);
    inv = rsqrtf(ss * (1.f/Cv) - mu*mu + EPSv);
    W = ((const float4*)w1)[t];  Bb = ((const float4*)b1)[t];
    float4 o;
    o.x = (h.x-mu)*inv*W.x + Bb.x;  o.y = (h.y-mu)*inv*W.y + Bb.y;
    o.z = (h.z-mu)*inv*W.z + Bb.z;  o.w = (h.w-mu)*inv*W.w + Bb.w;
    ((float4*)(g_xn + tok*Cv))[t] = o;
}

// single LN: in -> out
__global__ void __launch_bounds__(256) ln_kernel(
    const float* __restrict__ x, const float* __restrict__ w,
    const float* __restrict__ b, float* __restrict__ out)
{
    size_t tok = blockIdx.x;
    int t = threadIdx.x;
    float4 v = ((const float4*)(x + tok*Cv))[t];
    float s  = v.x + v.y + v.z + v.w;
    float ss = v.x*v.x + v.y*v.y + v.z*v.z + v.w*v.w;
    block_reduce2(s, ss);
    float mu  = s * (1.f/Cv);
    float inv = rsqrtf(ss * (1.f/Cv) - mu*mu + EPSv);
    float4 W = ((const float4*)w)[t], Bb = ((const float4*)b)[t];
    float4 o;
    o.x = (v.x-mu)*inv*W.x + Bb.x;  o.y = (v.y-mu)*inv*W.y + Bb.y;
    o.z = (v.z-mu)*inv*W.z + Bb.z;  o.w = (v.w-mu)*inv*W.w + Bb.w;
    ((float4*)(out + tok*Cv))[t] = o;
}

// ---------------- token-shift mixing ----------------
__device__ __forceinline__ float4 mix_one(float4 cur, float4 prev, float4 m) {
    float4 o;
    o.x = cur.x*m.x + prev.x*(1.f - m.x);
    o.y = cur.y*m.y + prev.y*(1.f - m.y);
    o.z = cur.z*m.z + prev.z*(1.f - m.z);
    o.w = cur.w*m.w + prev.w*(1.f - m.w);
    return o;
}

__global__ void __launch_bounds__(256) mix4_kernel(
    const float* __restrict__ xn,
    const float* __restrict__ tk, const float* __restrict__ tv,
    const float* __restrict__ tr, const float* __restrict__ tg)
{
    size_t i4 = (size_t)blockIdx.x*256 + threadIdx.x;   // over TOK*Cv/4
    int c4 = (int)(i4 & 255);
    size_t tc = i4 >> 8;
    float4 cur  = ((const float4*)xn)[i4];
    float4 prev = make_float4(0.f,0.f,0.f,0.f);
    if (tc & (Tv-1)) prev = ((const float4*)xn)[i4 - 256];
    ((float4*)g_b0)[i4] = mix_one(cur, prev, ((const float4*)tk)[c4]);
    ((float4*)g_b1)[i4] = mix_one(cur, prev, ((const float4*)tv)[c4]);
    ((float4*)g_b2)[i4] = mix_one(cur, prev, ((const float4*)tr)[c4]);
    ((float4*)g_b3)[i4] = mix_one(cur, prev, ((const float4*)tg)[c4]);
}

__global__ void __launch_bounds__(256) mix2_kernel(
    const float* __restrict__ xn,
    const float* __restrict__ tk, const float* __restrict__ tr)
{
    size_t i4 = (size_t)blockIdx.x*256 + threadIdx.x;
    int c4 = (int)(i4 & 255);
    size_t tc = i4 >> 8;
    float4 cur  = ((const float4*)xn)[i4];
    float4 prev = make_float4(0.f,0.f,0.f,0.f);
    if (tc & (Tv-1)) prev = ((const float4*)xn)[i4 - 256];
    ((float4*)g_b3)[i4] = mix_one(cur, prev, ((const float4*)tk)[c4]);   // ffn xk
    ((float4*)g_b2)[i4] = mix_one(cur, prev, ((const float4*)tr)[c4]);   // ffn xr
}

// ---------------- TF32 WMMA GEMM:  C[M,N] = A[M,K] @ W[N,K]^T  ----------------
// EPI: 0 none, 1 silu, 2 relu^2, 3 sigmoid, 4 residual add (C = Cres + A@W^T)
#define BMg 128
#define BNg 128
#define BKg 32
#define BKP 36

template<int EPI>
__global__ void __launch_bounds__(256) gemm_tn(
    const float* __restrict__ A, const float* __restrict__ W,
    const float* __restrict__ Cres, float* __restrict__ Co,
    int M, int N, int K)
{
    __shared__ __align__(16) float As[BMg*BKP];
    __shared__ __align__(16) float Bs[BNg*BKP];
    int tid  = threadIdx.x;
    int warp = tid >> 5;
    int wm = warp >> 1;   // 0..3 -> 32-row strip
    int wn = warp & 1;    // 0..1 -> 64-col strip

    wmma::fragment<wmma::accumulator,16,16,8,float> acc[2][4];
    #pragma unroll
    for (int i = 0; i < 2; i++)
        #pragma unroll
        for (int j = 0; j < 4; j++) wmma::fill_fragment(acc[i][j], 0.f);

    const float* Ab = A + (size_t)blockIdx.y*BMg*K;
    const float* Wb = W + (size_t)blockIdx.x*BNg*K;

    for (int k0 = 0; k0 < K; k0 += BKg) {
        __syncthreads();
        #pragma unroll
        for (int it = 0; it < 4; it++) {
            int i   = it*256 + tid;       // 0..1023
            int row = i >> 3;
            int c4  = i & 7;
            float4 va = *(const float4*)(Ab + (size_t)row*K + k0 + c4*4);
            va.x = tf32r(va.x); va.y = tf32r(va.y); va.z = tf32r(va.z); va.w = tf32r(va.w);
            *(float4*)(As + row*BKP + c4*4) = va;
            float4 vb = *(const float4*)(Wb + (size_t)row*K + k0 + c4*4);
            vb.x = tf32r(vb.x); vb.y = tf32r(vb.y); vb.z = tf32r(vb.z); vb.w = tf32r(vb.w);
            *(float4*)(Bs + row*BKP + c4*4) = vb;
        }
        __syncthreads();
        #pragma unroll
        for (int kk = 0; kk < 4; kk++) {
            wmma::fragment<wmma::matrix_a,16,16,8,wmma::precision::tf32,wmma::row_major> af[2];
            wmma::fragment<wmma::matrix_b,16,16,8,wmma::precision::tf32,wmma::col_major> bf[4];
            #pragma unroll
            for (int i = 0; i < 2; i++)
                wmma::load_matrix_sync(af[i], As + (wm*32 + i*16)*BKP + kk*8, BKP);
            #pragma unroll
            for (int j = 0; j < 4; j++)
                wmma::load_matrix_sync(bf[j], Bs + (wn*64 + j*16)*BKP + kk*8, BKP);
            #pragma unroll
            for (int i = 0; i < 2; i++)
                #pragma unroll
                for (int j = 0; j < 4; j++)
                    wmma::mma_sync(acc[i][j], af[i], bf[j], acc[i][j]);
        }
    }

    #pragma unroll
    for (int i = 0; i < 2; i++)
        #pragma unroll
        for (int j = 0; j < 4; j++) {
            size_t r0 = (size_t)blockIdx.y*BMg + wm*32 + i*16;
            size_t c0 = (size_t)blockIdx.x*BNg + wn*64 + j*16;
            float* cp = Co + r0*N + c0;
            if (EPI == 4) {
                wmma::fragment<wmma::accumulator,16,16,8,float> cr;
                wmma::load_matrix_sync(cr, Cres + r0*N + c0, N, wmma::mem_row_major);
                #pragma unroll
                for (int e = 0; e < acc[i][j].num_elements; e++) acc[i][j].x[e] += cr.x[e];
            }
            if (EPI == 1) {
                #pragma unroll
                for (int e = 0; e < acc[i][j].num_elements; e++) {
                    float v = acc[i][j].x[e];
                    acc[i][j].x[e] = v / (1.f + __expf(-v));
                }
            }
            if (EPI == 2) {
                #pragma unroll
                for (int e = 0; e < acc[i][j].num_elements; e++) {
                    float v = fmaxf(acc[i][j].x[e], 0.f);
                    acc[i][j].x[e] = v*v;
                }
            }
            if (EPI == 3) {
                #pragma unroll
                for (int e = 0; e < acc[i][j].num_elements; e++)
                    acc[i][j].x[e] = 1.f / (1.f + __expf(-acc[i][j].x[e]));
            }
            wmma::store_matrix_sync(cp, acc[i][j], N, wmma::mem_row_major);
        }
}

// ---------------- WKV5 sequential scan ----------------
// one block per (b,h); 256 threads; thread (ig,j) owns S[ig*16 .. ig*16+15][j]
__global__ void __launch_bounds__(256) wkv5_kernel(
    const float* __restrict__ r, const float* __restrict__ k, const float* __restrict__ v,
    const float* __restrict__ wdec, const float* __restrict__ u, float* __restrict__ y)
{
    int b = blockIdx.x >> 4;
    int h = blockIdx.x & 15;
    int tid = threadIdx.x;
    int j  = tid & 63;
    int ig = tid >> 6;
    __shared__ float rs[64], ks[64], vs[64];
    __shared__ float yred[4][64];
    float S[16], ew[16], uu[16];
    #pragma unroll
    for (int ii = 0; ii < 16; ii++) {
        int i = ig*16 + ii;
        double wv = (double)wdec[h*Nv + i];
        ew[ii] = (float)exp(-exp(wv));     // double precision: decay error compounds over T
        uu[ii] = u[h*Nv + i];
        S[ii]  = 0.f;
    }
    size_t base = ((size_t)b*Tv)*Cv + (size_t)h*Nv;
    for (int t = 0; t < Tv; t++, base += Cv) {
        if      (tid < 64)  rs[tid]      = r[base + tid];
        else if (tid < 128) ks[tid - 64] = k[base + tid - 64];
        else if (tid < 192) vs[tid - 128]= v[base + tid - 128];
        __syncthreads();
        float vj = vs[j];
        float yp = 0.f;
        #pragma unroll
        for (int ii = 0; ii < 16; ii++) {
            int i = ig*16 + ii;
            float kv = ks[i] * vj;
            yp    = fmaf(rs[i], fmaf(uu[ii], kv, S[ii]), yp);   // y uses pre-update S
            S[ii] = fmaf(ew[ii], S[ii], kv);
        }
        yred[ig][j] = yp;
        __syncthreads();
        if (tid < 64)
            y[base + tid] = yred[0][tid] + yred[1][tid] + yred[2][tid] + yred[3][tid];
        __syncthreads();
    }
}

// ---------------- groupnorm(y/8)*w+b then * silu(g) ----------------
__global__ void __launch_bounds__(512) gnmul_kernel(
    const float* __restrict__ y, const float* __restrict__ w, const float* __restrict__ b,
    const float* __restrict__ g, float* __restrict__ out)
{
    size_t tok = blockIdx.x;
    int wg = threadIdx.x >> 5, lane = threadIdx.x & 31;
    size_t base = tok*Cv + (size_t)wg*64;
    float a0 = y[base + lane]      * (1.f/HSDv);
    float a1 = y[base + lane + 32] * (1.f/HSDv);
    float s = a0 + a1, ss = a0*a0 + a1*a1;
    #pragma unroll
    for (int o = 16; o; o >>= 1) {
        s  += __shfl_xor_sync(0xffffffffu, s,  o);
        ss += __shfl_xor_sync(0xffffffffu, ss, o);
    }
    float mu  = s * (1.f/64.f);
    float inv = rsqrtf(ss * (1.f/64.f) - mu*mu + EPSv);
    int c0 = wg*64 + lane;
    out[base + lane]      = ((a0-mu)*inv*w[c0]      + b[c0])      * g[base + lane];
    out[base + lane + 32] = ((a1-mu)*inv*w[c0 + 32] + b[c0 + 32]) * g[base + lane + 32];
}

// ---------------- final: out = x + sigmoid(sr) * kv ----------------
__global__ void __launch_bounds__(256) final_kernel(float* __restrict__ out) {
    size_t i4 = (size_t)blockIdx.x*256 + threadIdx.x;
    float4 xv = ((const float4*)g_x )[i4];
    float4 sg = ((const float4*)g_b4)[i4];   // sigmoid already applied in GEMM epilogue
    float4 kv = ((const float4*)g_b5)[i4];
    float4 o;
    o.x = xv.x + sg.x*kv.x;  o.y = xv.y + sg.y*kv.y;
    o.z = xv.z + sg.z*kv.z;  o.w = xv.w + sg.w*kv.w;
    ((float4*)out)[i4] = o;
}

// ---------------- orchestration ----------------
extern "C" void kernel_launch(void* const* d_in, const int* in_sizes, int n_in,
                              void* d_out, int out_size)
{
    (void)in_sizes; (void)n_in; (void)out_size;
    const float* x     = (const float*)d_in[0];
    const float* ln0w  = (const float*)d_in[1];
    const float* ln0b  = (const float*)d_in[2];
    const float* ln1w  = (const float*)d_in[3];
    const float* ln1b  = (const float*)d_in[4];
    const float* ln2w  = (const float*)d_in[5];
    const float* ln2b  = (const float*)d_in[6];
    const float* tmk   = (const float*)d_in[7];
    const float* tmv   = (const float*)d_in[8];
    const float* tmr   = (const float*)d_in[9];
    const float* tmg   = (const float*)d_in[10];
    const float* decay = (const float*)d_in[11];
    const float* faaaa = (const float*)d_in[12];
    const float* Wr    = (const float*)d_in[13];
    const float* Wk    = (const float*)d_in[14];
    const float* Wv    = (const float*)d_in[15];
    const float* Wg    = (const float*)d_in[16];
    const float* Wo    = (const float*)d_in[17];
    const float* lnxw  = (const float*)d_in[18];
    const float* lnxb  = (const float*)d_in[19];
    const float* ftmk  = (const float*)d_in[20];
    const float* ftmr  = (const float*)d_in[21];
    const float* fWk   = (const float*)d_in[22];
    const float* fWr   = (const float*)d_in[23];
    const float* fWv   = (const float*)d_in[24];

    float *px, *pxn, *pb0, *pb1, *pb2, *pb3, *pb4, *pb5, *pb6, *pb7, *pbig;
    cudaGetSymbolAddress((void**)&px,   g_x);
    cudaGetSymbolAddress((void**)&pxn,  g_xn);
    cudaGetSymbolAddress((void**)&pb0,  g_b0);
    cudaGetSymbolAddress((void**)&pb1,  g_b1);
    cudaGetSymbolAddress((void**)&pb2,  g_b2);
    cudaGetSymbolAddress((void**)&pb3,  g_b3);
    cudaGetSymbolAddress((void**)&pb4,  g_b4);
    cudaGetSymbolAddress((void**)&pb5,  g_b5);
    cudaGetSymbolAddress((void**)&pb6,  g_b6);
    cudaGetSymbolAddress((void**)&pb7,  g_b7);
    cudaGetSymbolAddress((void**)&pbig, g_big);

    dim3 gCC(Cv/BNg,   TOK/BMg);   // (8, 128)
    dim3 gFF(FFNv/BNg, TOK/BMg);   // (28, 128)

    // ln0 + ln1
    ln0_ln1_kernel<<<TOK, 256>>>(x, ln0w, ln0b, ln1w, ln1b);
    // time-mix token shift
    mix4_kernel<<<TOK, 256>>>(pxn, tmk, tmv, tmr, tmg);
    // r, k, v, silu(g)
    gemm_tn<0><<<gCC, 256>>>(pb2, Wr, nullptr, pb4, TOK, Cv, Cv);
    gemm_tn<0><<<gCC, 256>>>(pb0, Wk, nullptr, pb5, TOK, Cv, Cv);
    gemm_tn<0><<<gCC, 256>>>(pb1, Wv, nullptr, pb6, TOK, Cv, Cv);
    gemm_tn<1><<<gCC, 256>>>(pb3, Wg, nullptr, pb7, TOK, Cv, Cv);
    // wkv5 scan: y -> g_b0
    wkv5_kernel<<<Bv*Hv, 256>>>(pb4, pb5, pb6, decay, faaaa, pb0);
    // groupnorm(y/8)*lnx * silu(g) -> g_b1
    gnmul_kernel<<<TOK, 512>>>(pb0, lnxw, lnxb, pb7, pb1);
    // x += gy @ Wo^T  (residual fold in epilogue)
    gemm_tn<4><<<gCC, 256>>>(pb1, Wo, px, px, TOK, Cv, Cv);
    // channel-mix
    ln_kernel<<<TOK, 256>>>(px, ln2w, ln2b, pxn);
    mix2_kernel<<<TOK, 256>>>(pxn, ftmk, ftmr);
    gemm_tn<2><<<gFF, 256>>>(pb3, fWk, nullptr, pbig, TOK, FFNv, Cv);  // relu^2
    gemm_tn<3><<<gCC, 256>>>(pb2, fWr, nullptr, pb4,  TOK, Cv, Cv);    // sigmoid
    gemm_tn<0><<<gCC, 256>>>(pbig, fWv, nullptr, pb5, TOK, Cv, FFNv);  // kv
    // out = x + sigmoid(sr)*kv
    final_kernel<<<TOK, 256>>>((float*)d_out);
}

// round 4
// speedup vs baseline: 1.0449x; 1.0449x over previous
#include <cuda_runtime.h>
#include <cuda_bf16.h>
#include <mma.h>
#include <cstdint>
#include <cstddef>

using namespace nvcuda;

#define Bv    8
#define Tv    2048
#define Cv    1024
#define Hv    16
#define Nv    64
#define FFNv  3584
#define TOK   (Bv*Tv)            // 16384 tokens
#define HSDv  8.0f
#define EPSv  1e-5f

// ---------------- scratch (static device arrays; no allocations) ----------------
__device__ float g_x  [(size_t)TOK*Cv];   // residual stream
__device__ float g_xn [(size_t)TOK*Cv];   // layernorm output
__device__ float g_b0 [(size_t)TOK*Cv];   // xk   -> later wkv y
__device__ float g_b1 [(size_t)TOK*Cv];   // xv   -> later gy
__device__ float g_b2 [(size_t)TOK*Cv];   // xr   -> later ffn xr
__device__ float g_b3 [(size_t)TOK*Cv];   // xg   -> later ffn xk
__device__ float g_b4 [(size_t)TOK*Cv];   // r    -> later sigmoid(ffn r)
__device__ float g_b5 [(size_t)TOK*Cv];   // k    -> later kv
__device__ float g_b6 [(size_t)TOK*Cv];   // v
__device__ float g_b7 [(size_t)TOK*Cv];   // silu(g)
__device__ float g_big[(size_t)TOK*FFNv]; // ffn hidden (relu^2)

// pre-rounded (tf32 RNA) weights
__device__ float g_wr [(size_t)Cv*Cv];
__device__ float g_wk [(size_t)Cv*Cv];
__device__ float g_wv [(size_t)Cv*Cv];
__device__ float g_wg [(size_t)Cv*Cv];
__device__ float g_wo [(size_t)Cv*Cv];
__device__ float g_fwk[(size_t)FFNv*Cv];
__device__ float g_fwr[(size_t)Cv*Cv];
__device__ float g_fwv[(size_t)Cv*FFNv];

// ---------------- helpers ----------------
__device__ __forceinline__ float tf32r(float x) {
    float y; asm("cvt.rna.tf32.f32 %0, %1;" : "=f"(y) : "f"(x)); return y;
}
__device__ __forceinline__ uint32_t smem_u32(const void* p) {
    uint32_t a;
    asm("{ .reg .u64 t; cvta.to.shared.u64 t, %1; cvt.u32.u64 %0, t; }" : "=r"(a) : "l"(p));
    return a;
}
__device__ __forceinline__ void cpa16(uint32_t s, const float* g) {
    asm volatile("cp.async.cg.shared.global [%0], [%1], 16;" :: "r"(s), "l"(g));
}
#define CPA_COMMIT() asm volatile("cp.async.commit_group;" ::: "memory")
#define CPA_WAIT0()  asm volatile("cp.async.wait_group 0;" ::: "memory")
#define CPA_WAIT1()  asm volatile("cp.async.wait_group 1;" ::: "memory")

// weight pre-rounding: dst[i] = tf32_rna(src[i])
__global__ void __launch_bounds__(256) convw_kernel(const float* __restrict__ src,
                                                    float* __restrict__ dst, int n4) {
    int i = blockIdx.x*256 + threadIdx.x;
    if (i >= n4) return;
    float4 v = ((const float4*)src)[i];
    v.x = tf32r(v.x); v.y = tf32r(v.y); v.z = tf32r(v.z); v.w = tf32r(v.w);
    ((float4*)dst)[i] = v;
}

// ---------------- TF32 WMMA GEMM:  C[M,N] = A[M,K] @ W[N,K]^T ----------------
// double-buffered cp.async pipeline; A and W must already be tf32-rounded.
// EPI: 0 none, 1 silu, 2 relu^2 (tf32 round), 3 sigmoid, 4 residual add
#define BMg 128
#define BNg 128
#define BKg 32
#define BKP 36
#define STG_F (BMg*BKP + BNg*BKP)          // floats per stage (9216)
#define GSMEM (2*STG_F*4)                  // 73728 bytes

__device__ __forceinline__ void load_chunk(const float* __restrict__ Ab,
                                           const float* __restrict__ Wb,
                                           int K, int kc, float* As, float* Bs, int tid) {
    #pragma unroll
    for (int it = 0; it < 4; it++) {
        int idx = it*256 + tid;          // 0..1023
        int row = idx >> 3, c4 = idx & 7;
        cpa16(smem_u32(As + row*BKP + c4*4), Ab + (size_t)row*K + kc + c4*4);
        cpa16(smem_u32(Bs + row*BKP + c4*4), Wb + (size_t)row*K + kc + c4*4);
    }
}

template<int EPI>
__global__ void __launch_bounds__(256, 2) gemm_tn(
    const float* __restrict__ A, const float* __restrict__ W,
    const float* __restrict__ Cres, float* __restrict__ Co,
    int N, int K)
{
    extern __shared__ __align__(16) float sm[];
    float* As[2] = { sm,             sm + STG_F };
    float* Bs[2] = { sm + BMg*BKP,   sm + STG_F + BMg*BKP };

    int tid  = threadIdx.x;
    int warp = tid >> 5;
    int wm = warp >> 1;   // 0..3 -> 32-row strip
    int wn = warp & 1;    // 0..1 -> 64-col strip

    wmma::fragment<wmma::accumulator,16,16,8,float> acc[2][4];
    #pragma unroll
    for (int i = 0; i < 2; i++)
        #pragma unroll
        for (int j = 0; j < 4; j++) wmma::fill_fragment(acc[i][j], 0.f);

    const float* Ab = A + (size_t)blockIdx.y*BMg*K;
    const float* Wb = W + (size_t)blockIdx.x*BNg*K;
    const int NC = K / BKg;

    load_chunk(Ab, Wb, K, 0, As[0], Bs[0], tid);
    CPA_COMMIT();

    for (int c = 0; c < NC; c++) {
        if (c + 1 < NC) {
            load_chunk(Ab, Wb, K, (c+1)*BKg, As[(c+1)&1], Bs[(c+1)&1], tid);
            CPA_COMMIT();
            CPA_WAIT1();
        } else {
            CPA_WAIT0();
        }
        __syncthreads();
        const float* Ac = As[c&1];
        const float* Bc = Bs[c&1];
        #pragma unroll
        for (int kk = 0; kk < 4; kk++) {
            wmma::fragment<wmma::matrix_a,16,16,8,wmma::precision::tf32,wmma::row_major> af[2];
            wmma::fragment<wmma::matrix_b,16,16,8,wmma::precision::tf32,wmma::col_major> bf[4];
            #pragma unroll
            for (int i = 0; i < 2; i++)
                wmma::load_matrix_sync(af[i], Ac + (wm*32 + i*16)*BKP + kk*8, BKP);
            #pragma unroll
            for (int j = 0; j < 4; j++)
                wmma::load_matrix_sync(bf[j], Bc + (wn*64 + j*16)*BKP + kk*8, BKP);
            #pragma unroll
            for (int i = 0; i < 2; i++)
                #pragma unroll
                for (int j = 0; j < 4; j++)
                    wmma::mma_sync(acc[i][j], af[i], bf[j], acc[i][j]);
        }
        __syncthreads();
    }

    #pragma unroll
    for (int i = 0; i < 2; i++)
        #pragma unroll
        for (int j = 0; j < 4; j++) {
            size_t r0 = (size_t)blockIdx.y*BMg + wm*32 + i*16;
            size_t c0 = (size_t)blockIdx.x*BNg + wn*64 + j*16;
            float* cp = Co + r0*N + c0;
            if (EPI == 4) {
                wmma::fragment<wmma::accumulator,16,16,8,float> cr;
                wmma::load_matrix_sync(cr, Cres + r0*N + c0, N, wmma::mem_row_major);
                #pragma unroll
                for (int e = 0; e < acc[i][j].num_elements; e++) acc[i][j].x[e] += cr.x[e];
            }
            if (EPI == 1) {
                #pragma unroll
                for (int e = 0; e < acc[i][j].num_elements; e++) {
                    float v = acc[i][j].x[e];
                    acc[i][j].x[e] = v / (1.f + __expf(-v));
                }
            }
            if (EPI == 2) {
                #pragma unroll
                for (int e = 0; e < acc[i][j].num_elements; e++) {
                    float v = fmaxf(acc[i][j].x[e], 0.f);
                    acc[i][j].x[e] = tf32r(v*v);   // feeds next GEMM: pre-round
                }
            }
            if (EPI == 3) {
                #pragma unroll
                for (int e = 0; e < acc[i][j].num_elements; e++)
                    acc[i][j].x[e] = 1.f / (1.f + __expf(-acc[i][j].x[e]));
            }
            wmma::store_matrix_sync(cp, acc[i][j], N, wmma::mem_row_major);
        }
}

// ---------------- reductions / LN ----------------
__device__ __forceinline__ void block_reduce2(float& s, float& ss) {
    __shared__ float red[64];
    __syncthreads();
    #pragma unroll
    for (int o = 16; o; o >>= 1) {
        s  += __shfl_xor_sync(0xffffffffu, s,  o);
        ss += __shfl_xor_sync(0xffffffffu, ss, o);
    }
    int lane = threadIdx.x & 31, w = threadIdx.x >> 5;
    if (lane == 0) { red[w] = s; red[32 + w] = ss; }
    __syncthreads();
    if (w == 0) {
        float a = (lane < 8) ? red[lane]      : 0.f;
        float c = (lane < 8) ? red[32 + lane] : 0.f;
        #pragma unroll
        for (int o = 4; o; o >>= 1) {
            a += __shfl_xor_sync(0xffffffffu, a, o);
            c += __shfl_xor_sync(0xffffffffu, c, o);
        }
        if (lane == 0) { red[0] = a; red[32] = c; }
    }
    __syncthreads();
    s = red[0]; ss = red[32];
}

__global__ void __launch_bounds__(256) ln0_ln1_kernel(
    const float* __restrict__ x,
    const float* __restrict__ w0, const float* __restrict__ b0,
    const float* __restrict__ w1, const float* __restrict__ b1)
{
    size_t tok = blockIdx.x;
    int t = threadIdx.x;
    float4 v = ((const float4*)(x + tok*Cv))[t];
    float s  = v.x + v.y + v.z + v.w;
    float ss = v.x*v.x + v.y*v.y + v.z*v.z + v.w*v.w;
    block_reduce2(s, ss);
    float mu  = s * (1.f/Cv);
    float inv = rsqrtf(ss * (1.f/Cv) - mu*mu + EPSv);
    float4 W = ((const float4*)w0)[t], Bb = ((const float4*)b0)[t];
    float4 h;
    h.x = (v.x-mu)*inv*W.x + Bb.x;  h.y = (v.y-mu)*inv*W.y + Bb.y;
    h.z = (v.z-mu)*inv*W.z + Bb.z;  h.w = (v.w-mu)*inv*W.w + Bb.w;
    ((float4*)(g_x + tok*Cv))[t] = h;
    s  = h.x + h.y + h.z + h.w;
    ss = h.x*h.x + h.y*h.y + h.z*h.z + h.w*h.w;
    block_reduce2(s, ss);
    mu  = s * (1.f/Cv);
    inv = rsqrtf(ss * (1.f/Cv) - mu*mu + EPSv);
    W = ((const float4*)w1)[t];  Bb = ((const float4*)b1)[t];
    float4 o;
    o.x = (h.x-mu)*inv*W.x + Bb.x;  o.y = (h.y-mu)*inv*W.y + Bb.y;
    o.z = (h.z-mu)*inv*W.z + Bb.z;  o.w = (h.w-mu)*inv*W.w + Bb.w;
    ((float4*)(g_xn + tok*Cv))[t] = o;
}

__global__ void __launch_bounds__(256) ln_kernel(
    const float* __restrict__ x, const float* __restrict__ w,
    const float* __restrict__ b, float* __restrict__ out)
{
    size_t tok = blockIdx.x;
    int t = threadIdx.x;
    float4 v = ((const float4*)(x + tok*Cv))[t];
    float s  = v.x + v.y + v.z + v.w;
    float ss = v.x*v.x + v.y*v.y + v.z*v.z + v.w*v.w;
    block_reduce2(s, ss);
    float mu  = s * (1.f/Cv);
    float inv = rsqrtf(ss * (1.f/Cv) - mu*mu + EPSv);
    float4 W = ((const float4*)w)[t], Bb = ((const float4*)b)[t];
    float4 o;
    o.x = (v.x-mu)*inv*W.x + Bb.x;  o.y = (v.y-mu)*inv*W.y + Bb.y;
    o.z = (v.z-mu)*inv*W.z + Bb.z;  o.w = (v.w-mu)*inv*W.w + Bb.w;
    ((float4*)(out + tok*Cv))[t] = o;
}

// ---------------- token-shift mixing (outputs tf32-rounded: feed GEMMs) -------
__device__ __forceinline__ float4 mix_one_r(float4 cur, float4 prev, float4 m) {
    float4 o;
    o.x = tf32r(cur.x*m.x + prev.x*(1.f - m.x));
    o.y = tf32r(cur.y*m.y + prev.y*(1.f - m.y));
    o.z = tf32r(cur.z*m.z + prev.z*(1.f - m.z));
    o.w = tf32r(cur.w*m.w + prev.w*(1.f - m.w));
    return o;
}

__global__ void __launch_bounds__(256) mix4_kernel(
    const float* __restrict__ xn,
    const float* __restrict__ tk, const float* __restrict__ tv,
    const float* __restrict__ tr, const float* __restrict__ tg)
{
    size_t i4 = (size_t)blockIdx.x*256 + threadIdx.x;
    int c4 = (int)(i4 & 255);
    size_t tc = i4 >> 8;
    float4 cur  = ((const float4*)xn)[i4];
    float4 prev = make_float4(0.f,0.f,0.f,0.f);
    if (tc & (Tv-1)) prev = ((const float4*)xn)[i4 - 256];
    ((float4*)g_b0)[i4] = mix_one_r(cur, prev, ((const float4*)tk)[c4]);
    ((float4*)g_b1)[i4] = mix_one_r(cur, prev, ((const float4*)tv)[c4]);
    ((float4*)g_b2)[i4] = mix_one_r(cur, prev, ((const float4*)tr)[c4]);
    ((float4*)g_b3)[i4] = mix_one_r(cur, prev, ((const float4*)tg)[c4]);
}

__global__ void __launch_bounds__(256) mix2_kernel(
    const float* __restrict__ xn,
    const float* __restrict__ tk, const float* __restrict__ tr)
{
    size_t i4 = (size_t)blockIdx.x*256 + threadIdx.x;
    int c4 = (int)(i4 & 255);
    size_t tc = i4 >> 8;
    float4 cur  = ((const float4*)xn)[i4];
    float4 prev = make_float4(0.f,0.f,0.f,0.f);
    if (tc & (Tv-1)) prev = ((const float4*)xn)[i4 - 256];
    ((float4*)g_b3)[i4] = mix_one_r(cur, prev, ((const float4*)tk)[c4]);
    ((float4*)g_b2)[i4] = mix_one_r(cur, prev, ((const float4*)tr)[c4]);
}

// ---------------- WKV5 sequential scan ----------------
__global__ void __launch_bounds__(256) wkv5_kernel(
    const float* __restrict__ r, const float* __restrict__ k, const float* __restrict__ v,
    const float* __restrict__ wdec, const float* __restrict__ u, float* __restrict__ y)
{
    int b = blockIdx.x >> 4;
    int h = blockIdx.x & 15;
    int tid = threadIdx.x;
    int j  = tid & 63;
    int ig = tid >> 6;
    __shared__ float rs[64], ks[64], vs[64];
    __shared__ float yred[4][64];
    float S[16], ew[16], uu[16];
    #pragma unroll
    for (int ii = 0; ii < 16; ii++) {
        int i = ig*16 + ii;
        double wv = (double)wdec[h*Nv + i];
        ew[ii] = (float)exp(-exp(wv));
        uu[ii] = u[h*Nv + i];
        S[ii]  = 0.f;
    }
    size_t base = ((size_t)b*Tv)*Cv + (size_t)h*Nv;
    for (int t = 0; t < Tv; t++, base += Cv) {
        if      (tid < 64)  rs[tid]       = r[base + tid];
        else if (tid < 128) ks[tid - 64]  = k[base + tid - 64];
        else if (tid < 192) vs[tid - 128] = v[base + tid - 128];
        __syncthreads();
        float vj = vs[j];
        float yp = 0.f;
        #pragma unroll
        for (int ii = 0; ii < 16; ii++) {
            int i = ig*16 + ii;
            float kv = ks[i] * vj;
            yp    = fmaf(rs[i], fmaf(uu[ii], kv, S[ii]), yp);
            S[ii] = fmaf(ew[ii], S[ii], kv);
        }
        yred[ig][j] = yp;
        __syncthreads();
        if (tid < 64)
            y[base + tid] = yred[0][tid] + yred[1][tid] + yred[2][tid] + yred[3][tid];
        __syncthreads();
    }
}

// ---------------- groupnorm(y/8)*w+b then * silu(g); tf32-rounded (feeds Wo) --
__global__ void __launch_bounds__(512) gnmul_kernel(
    const float* __restrict__ y, const float* __restrict__ w, const float* __restrict__ b,
    const float* __restrict__ g, float* __restrict__ out)
{
    size_t tok = blockIdx.x;
    int wg = threadIdx.x >> 5, lane = threadIdx.x & 31;
    size_t base = tok*Cv + (size_t)wg*64;
    float a0 = y[base + lane]      * (1.f/HSDv);
    float a1 = y[base + lane + 32] * (1.f/HSDv);
    float s = a0 + a1, ss = a0*a0 + a1*a1;
    #pragma unroll
    for (int o = 16; o; o >>= 1) {
        s  += __shfl_xor_sync(0xffffffffu, s,  o);
        ss += __shfl_xor_sync(0xffffffffu, ss, o);
    }
    float mu  = s * (1.f/64.f);
    float inv = rsqrtf(ss * (1.f/64.f) - mu*mu + EPSv);
    int c0 = wg*64 + lane;
    out[base + lane]      = tf32r(((a0-mu)*inv*w[c0]      + b[c0])      * g[base + lane]);
    out[base + lane + 32] = tf32r(((a1-mu)*inv*w[c0 + 32] + b[c0 + 32]) * g[base + lane + 32]);
}

// ---------------- final: out = x + sigmoid(sr)*kv ----------------
__global__ void __launch_bounds__(256) final_kernel(float* __restrict__ out) {
    size_t i4 = (size_t)blockIdx.x*256 + threadIdx.x;
    float4 xv = ((const float4*)g_x )[i4];
    float4 sg = ((const float4*)g_b4)[i4];
    float4 kv = ((const float4*)g_b5)[i4];
    float4 o;
    o.x = xv.x + sg.x*kv.x;  o.y = xv.y + sg.y*kv.y;
    o.z = xv.z + sg.z*kv.z;  o.w = xv.w + sg.w*kv.w;
    ((float4*)out)[i4] = o;
}

// ---------------- orchestration ----------------
extern "C" void kernel_launch(void* const* d_in, const int* in_sizes, int n_in,
                              void* d_out, int out_size)
{
    (void)in_sizes; (void)n_in; (void)out_size;
    const float* x     = (const float*)d_in[0];
    const float* ln0w  = (const float*)d_in[1];
    const float* ln0b  = (const float*)d_in[2];
    const float* ln1w  = (const float*)d_in[3];
    const float* ln1b  = (const float*)d_in[4];
    const float* ln2w  = (const float*)d_in[5];
    const float* ln2b  = (const float*)d_in[6];
    const float* tmk   = (const float*)d_in[7];
    const float* tmv   = (const float*)d_in[8];
    const float* tmr   = (const float*)d_in[9];
    const float* tmg   = (const float*)d_in[10];
    const float* decay = (const float*)d_in[11];
    const float* faaaa = (const float*)d_in[12];
    const float* Wr    = (const float*)d_in[13];
    const float* Wk    = (const float*)d_in[14];
    const float* Wv    = (const float*)d_in[15];
    const float* Wg    = (const float*)d_in[16];
    const float* Wo    = (const float*)d_in[17];
    const float* lnxw  = (const float*)d_in[18];
    const float* lnxb  = (const float*)d_in[19];
    const float* ftmk  = (const float*)d_in[20];
    const float* ftmr  = (const float*)d_in[21];
    const float* fWk   = (const float*)d_in[22];
    const float* fWr   = (const float*)d_in[23];
    const float* fWv   = (const float*)d_in[24];

    float *px, *pxn, *pb0, *pb1, *pb2, *pb3, *pb4, *pb5, *pb6, *pb7, *pbig;
    float *pwr, *pwk, *pwv, *pwg, *pwo, *pfwk, *pfwr, *pfwv;
    cudaGetSymbolAddress((void**)&px,   g_x);
    cudaGetSymbolAddress((void**)&pxn,  g_xn);
    cudaGetSymbolAddress((void**)&pb0,  g_b0);
    cudaGetSymbolAddress((void**)&pb1,  g_b1);
    cudaGetSymbolAddress((void**)&pb2,  g_b2);
    cudaGetSymbolAddress((void**)&pb3,  g_b3);
    cudaGetSymbolAddress((void**)&pb4,  g_b4);
    cudaGetSymbolAddress((void**)&pb5,  g_b5);
    cudaGetSymbolAddress((void**)&pb6,  g_b6);
    cudaGetSymbolAddress((void**)&pb7,  g_b7);
    cudaGetSymbolAddress((void**)&pbig, g_big);
    cudaGetSymbolAddress((void**)&pwr,  g_wr);
    cudaGetSymbolAddress((void**)&pwk,  g_wk);
    cudaGetSymbolAddress((void**)&pwv,  g_wv);
    cudaGetSymbolAddress((void**)&pwg,  g_wg);
    cudaGetSymbolAddress((void**)&pwo,  g_wo);
    cudaGetSymbolAddress((void**)&pfwk, g_fwk);
    cudaGetSymbolAddress((void**)&pfwr, g_fwr);
    cudaGetSymbolAddress((void**)&pfwv, g_fwv);

    cudaFuncSetAttribute(gemm_tn<0>, cudaFuncAttributeMaxDynamicSharedMemorySize, GSMEM);
    cudaFuncSetAttribute(gemm_tn<1>, cudaFuncAttributeMaxDynamicSharedMemorySize, GSMEM);
    cudaFuncSetAttribute(gemm_tn<2>, cudaFuncAttributeMaxDynamicSharedMemorySize, GSMEM);
    cudaFuncSetAttribute(gemm_tn<3>, cudaFuncAttributeMaxDynamicSharedMemorySize, GSMEM);
    cudaFuncSetAttribute(gemm_tn<4>, cudaFuncAttributeMaxDynamicSharedMemorySize, GSMEM);

    const int nCC4 = Cv*Cv/4, nFF4 = FFNv*Cv/4;
    // weight pre-rounding (tf32 RNA)
    convw_kernel<<<(nCC4+255)/256, 256>>>(Wr,  pwr,  nCC4);
    convw_kernel<<<(nCC4+255)/256, 256>>>(Wk,  pwk,  nCC4);
    convw_kernel<<<(nCC4+255)/256, 256>>>(Wv,  pwv,  nCC4);
    convw_kernel<<<(nCC4+255)/256, 256>>>(Wg,  pwg,  nCC4);
    convw_kernel<<<(nCC4+255)/256, 256>>>(Wo,  pwo,  nCC4);
    convw_kernel<<<(nFF4+255)/256, 256>>>(fWk, pfwk, nFF4);
    convw_kernel<<<(nCC4+255)/256, 256>>>(fWr, pfwr, nCC4);
    convw_kernel<<<(nFF4+255)/256, 256>>>(fWv, pfwv, nFF4);

    dim3 gCC(Cv/BNg,   TOK/BMg);   // (8, 128)
    dim3 gFF(FFNv/BNg, TOK/BMg);   // (28, 128)

    ln0_ln1_kernel<<<TOK, 256>>>(x, ln0w, ln0b, ln1w, ln1b);
    mix4_kernel<<<TOK, 256>>>(pxn, tmk, tmv, tmr, tmg);
    gemm_tn<0><<<gCC, 256, GSMEM>>>(pb2, pwr, nullptr, pb4, Cv, Cv);
    gemm_tn<0><<<gCC, 256, GSMEM>>>(pb0, pwk, nullptr, pb5, Cv, Cv);
    gemm_tn<0><<<gCC, 256, GSMEM>>>(pb1, pwv, nullptr, pb6, Cv, Cv);
    gemm_tn<1><<<gCC, 256, GSMEM>>>(pb3, pwg, nullptr, pb7, Cv, Cv);
    wkv5_kernel<<<Bv*Hv, 256>>>(pb4, pb5, pb6, decay, faaaa, pb0);
    gnmul_kernel<<<TOK, 512>>>(pb0, lnxw, lnxb, pb7, pb1);
    gemm_tn<4><<<gCC, 256, GSMEM>>>(pb1, pwo, px, px, Cv, Cv);
    ln_kernel<<<TOK, 256>>>(px, ln2w, ln2b, pxn);
    mix2_kernel<<<TOK, 256>>>(pxn, ftmk, ftmr);
    gemm_tn<2><<<gFF, 256, GSMEM>>>(pb3, pfwk, nullptr, pbig, FFNv, Cv);
    gemm_tn<3><<<gCC, 256, GSMEM>>>(pb2, pfwr, nullptr, pb4,  Cv, Cv);
    gemm_tn<0><<<gCC, 256, GSMEM>>>(pbig, pfwv, nullptr, pb5, Cv, FFNv);
    final_kernel<<<TOK, 256>>>((float*)d_out);
}

// round 6
// speedup vs baseline: 2.2682x; 2.1707x over previous
#include <cuda_runtime.h>
#include <cuda_fp16.h>
#include <mma.h>
#include <cstdint>
#include <cstddef>

using namespace nvcuda;

#define Bv    8
#define Tv    2048
#define Cv    1024
#define Hv    16
#define Nv    64
#define FFNv  3584
#define TOK   (Bv*Tv)            // 16384 tokens
#define HSDv  8.0f
#define EPSv  1e-5f

// ---------------- fp32 scratch ----------------
__device__ float g_x  [(size_t)TOK*Cv];   // residual stream
__device__ float g_xn [(size_t)TOK*Cv];   // layernorm output
__device__ float g_r  [(size_t)TOK*Cv];
__device__ float g_k  [(size_t)TOK*Cv];
__device__ float g_v  [(size_t)TOK*Cv];
__device__ float g_g  [(size_t)TOK*Cv];   // silu(g)
__device__ float g_y  [(size_t)TOK*Cv];   // wkv output
__device__ float g_sr [(size_t)TOK*Cv];   // sigmoid(ffn r)
__device__ float g_kv [(size_t)TOK*Cv];
__device__ float g_big[(size_t)TOK*FFNv]; // relu^2 hidden fp32

// ---------------- fp16 scratch (GEMM operands) ----------------
__device__ __half h_xk [(size_t)TOK*Cv];
__device__ __half h_xv [(size_t)TOK*Cv];
__device__ __half h_xr [(size_t)TOK*Cv];
__device__ __half h_xg [(size_t)TOK*Cv];
__device__ __half h_gy [(size_t)TOK*Cv];
__device__ __half h_fxk[(size_t)TOK*Cv];
__device__ __half h_fxr[(size_t)TOK*Cv];
__device__ __half h_big[(size_t)TOK*FFNv];
__device__ __half h_wr [(size_t)Cv*Cv];
__device__ __half h_wk [(size_t)Cv*Cv];
__device__ __half h_wv [(size_t)Cv*Cv];
__device__ __half h_wg [(size_t)Cv*Cv];
__device__ __half h_wo [(size_t)Cv*Cv];
__device__ __half h_fwk[(size_t)FFNv*Cv];
__device__ __half h_fwr[(size_t)Cv*Cv];
__device__ __half h_fwv[(size_t)Cv*FFNv];

struct half4 { __half2 lo, hi; };

// ---------------- helpers ----------------
__device__ __forceinline__ uint32_t smem_u32(const void* p) {
    uint32_t a;
    asm("{ .reg .u64 t; cvta.to.shared.u64 t, %1; cvt.u32.u64 %0, t; }" : "=r"(a) : "l"(p));
    return a;
}
__device__ __forceinline__ void cpa16(uint32_t s, const void* g) {
    asm volatile("cp.async.cg.shared.global [%0], [%1], 16;" :: "r"(s), "l"(g));
}
#define CPA_COMMIT() asm volatile("cp.async.commit_group;" ::: "memory")
#define CPA_WAIT0()  asm volatile("cp.async.wait_group 0;" ::: "memory")
#define CPA_WAIT1()  asm volatile("cp.async.wait_group 1;" ::: "memory")

// float -> half conversion (for weights and the FFN hidden)
__global__ void __launch_bounds__(256) convh_kernel(const float* __restrict__ src,
                                                    __half* __restrict__ dst, int n4) {
    int i = blockIdx.x*256 + threadIdx.x;
    if (i >= n4) return;
    float4 v = ((const float4*)src)[i];
    half4 o;
    o.lo = __floats2half2_rn(v.x, v.y);
    o.hi = __floats2half2_rn(v.z, v.w);
    ((half4*)dst)[i] = o;
}

// ---------------- FP16 WMMA GEMM:  C[M,N] = A[M,K] @ W[N,K]^T ----------------
// A, W half (pre-rounded); C fp32. cp.async double-buffered, BK=64.
// EPI: 0 none, 1 silu, 2 relu^2, 3 sigmoid, 4 residual add
#define BMg 128
#define BNg 128
#define BKg 64
#define BKP 72                              // halves (+16B pad)
#define STG_H ((BMg+BNg)*BKP)               // halves per stage (18432)
#define GSMEM (2*STG_H*2)                   // 73728 bytes

__device__ __forceinline__ void load_chunk(const __half* __restrict__ Ab,
                                           const __half* __restrict__ Wb,
                                           int K, int kc, __half* As, __half* Bs, int tid) {
    #pragma unroll
    for (int it = 0; it < 4; it++) {
        int idx = it*256 + tid;          // 0..1023
        int row = idx >> 3, c8 = idx & 7;
        cpa16(smem_u32(As + row*BKP + c8*8), Ab + (size_t)row*K + kc + c8*8);
        cpa16(smem_u32(Bs + row*BKP + c8*8), Wb + (size_t)row*K + kc + c8*8);
    }
}

template<int EPI>
__global__ void __launch_bounds__(256, 2) gemm_h(
    const __half* __restrict__ A, const __half* __restrict__ W,
    const float* __restrict__ Cres, float* __restrict__ Co,
    int N, int K)
{
    extern __shared__ __align__(16) __half sm[];
    __half* As[2] = { sm,             sm + STG_H };
    __half* Bs[2] = { sm + BMg*BKP,   sm + STG_H + BMg*BKP };

    int tid  = threadIdx.x;
    int warp = tid >> 5;
    int wm = warp >> 1;   // 0..3 -> 32-row strip
    int wn = warp & 1;    // 0..1 -> 64-col strip

    wmma::fragment<wmma::accumulator,16,16,16,float> acc[2][4];
    #pragma unroll
    for (int i = 0; i < 2; i++)
        #pragma unroll
        for (int j = 0; j < 4; j++) wmma::fill_fragment(acc[i][j], 0.f);

    const __half* Ab = A + (size_t)blockIdx.y*BMg*K;
    const __half* Wb = W + (size_t)blockIdx.x*BNg*K;
    const int NC = K / BKg;

    load_chunk(Ab, Wb, K, 0, As[0], Bs[0], tid);
    CPA_COMMIT();

    for (int c = 0; c < NC; c++) {
        if (c + 1 < NC) {
            load_chunk(Ab, Wb, K, (c+1)*BKg, As[(c+1)&1], Bs[(c+1)&1], tid);
            CPA_COMMIT();
            CPA_WAIT1();
        } else {
            CPA_WAIT0();
        }
        __syncthreads();
        const __half* Ac = As[c&1];
        const __half* Bc = Bs[c&1];
        #pragma unroll
        for (int kk = 0; kk < 4; kk++) {
            wmma::fragment<wmma::matrix_a,16,16,16,__half,wmma::row_major> af[2];
            wmma::fragment<wmma::matrix_b,16,16,16,__half,wmma::col_major> bf[4];
            #pragma unroll
            for (int i = 0; i < 2; i++)
                wmma::load_matrix_sync(af[i], Ac + (wm*32 + i*16)*BKP + kk*16, BKP);
            #pragma unroll
            for (int j = 0; j < 4; j++)
                wmma::load_matrix_sync(bf[j], Bc + (wn*64 + j*16)*BKP + kk*16, BKP);
            #pragma unroll
            for (int i = 0; i < 2; i++)
                #pragma unroll
                for (int j = 0; j < 4; j++)
                    wmma::mma_sync(acc[i][j], af[i], bf[j], acc[i][j]);
        }
        __syncthreads();
    }

    #pragma unroll
    for (int i = 0; i < 2; i++)
        #pragma unroll
        for (int j = 0; j < 4; j++) {
            size_t r0 = (size_t)blockIdx.y*BMg + wm*32 + i*16;
            size_t c0 = (size_t)blockIdx.x*BNg + wn*64 + j*16;
            float* cp = Co + r0*N + c0;
            if (EPI == 4) {
                wmma::fragment<wmma::accumulator,16,16,16,float> cr;
                wmma::load_matrix_sync(cr, Cres + r0*N + c0, N, wmma::mem_row_major);
                #pragma unroll
                for (int e = 0; e < acc[i][j].num_elements; e++) acc[i][j].x[e] += cr.x[e];
            }
            if (EPI == 1) {
                #pragma unroll
                for (int e = 0; e < acc[i][j].num_elements; e++) {
                    float v = acc[i][j].x[e];
                    acc[i][j].x[e] = v / (1.f + __expf(-v));
                }
            }
            if (EPI == 2) {
                #pragma unroll
                for (int e = 0; e < acc[i][j].num_elements; e++) {
                    float v = fmaxf(acc[i][j].x[e], 0.f);
                    acc[i][j].x[e] = v*v;
                }
            }
            if (EPI == 3) {
                #pragma unroll
                for (int e = 0; e < acc[i][j].num_elements; e++)
                    acc[i][j].x[e] = 1.f / (1.f + __expf(-acc[i][j].x[e]));
            }
            wmma::store_matrix_sync(cp, acc[i][j], N, wmma::mem_row_major);
        }
}

// ---------------- reductions / LN ----------------
__device__ __forceinline__ void block_reduce2(float& s, float& ss) {
    __shared__ float red[64];
    __syncthreads();
    #pragma unroll
    for (int o = 16; o; o >>= 1) {
        s  += __shfl_xor_sync(0xffffffffu, s,  o);
        ss += __shfl_xor_sync(0xffffffffu, ss, o);
    }
    int lane = threadIdx.x & 31, w = threadIdx.x >> 5;
    if (lane == 0) { red[w] = s; red[32 + w] = ss; }
    __syncthreads();
    if (w == 0) {
        float a = (lane < 8) ? red[lane]      : 0.f;
        float c = (lane < 8) ? red[32 + lane] : 0.f;
        #pragma unroll
        for (int o = 4; o; o >>= 1) {
            a += __shfl_xor_sync(0xffffffffu, a, o);
            c += __shfl_xor_sync(0xffffffffu, c, o);
        }
        if (lane == 0) { red[0] = a; red[32] = c; }
    }
    __syncthreads();
    s = red[0]; ss = red[32];
}

__global__ void __launch_bounds__(256) ln0_ln1_kernel(
    const float* __restrict__ x,
    const float* __restrict__ w0, const float* __restrict__ b0,
    const float* __restrict__ w1, const float* __restrict__ b1)
{
    size_t tok = blockIdx.x;
    int t = threadIdx.x;
    float4 v = ((const float4*)(x + tok*Cv))[t];
    float s  = v.x + v.y + v.z + v.w;
    float ss = v.x*v.x + v.y*v.y + v.z*v.z + v.w*v.w;
    block_reduce2(s, ss);
    float mu  = s * (1.f/Cv);
    float inv = rsqrtf(ss * (1.f/Cv) - mu*mu + EPSv);
    float4 W = ((const float4*)w0)[t], Bb = ((const float4*)b0)[t];
    float4 h;
    h.x = (v.x-mu)*inv*W.x + Bb.x;  h.y = (v.y-mu)*inv*W.y + Bb.y;
    h.z = (v.z-mu)*inv*W.z + Bb.z;  h.w = (v.w-mu)*inv*W.w + Bb.w;
    ((float4*)(g_x + tok*Cv))[t] = h;
    s  = h.x + h.y + h.z + h.w;
    ss = h.x*h.x + h.y*h.y + h.z*h.z + h.w*h.w;
    block_reduce2(s, ss);
    mu  = s * (1.f/Cv);
    inv = rsqrtf(ss * (1.f/Cv) - mu*mu + EPSv);
    W = ((const float4*)w1)[t];  Bb = ((const float4*)b1)[t];
    float4 o;
    o.x = (h.x-mu)*inv*W.x + Bb.x;  o.y = (h.y-mu)*inv*W.y + Bb.y;
    o.z = (h.z-mu)*inv*W.z + Bb.z;  o.w = (h.w-mu)*inv*W.w + Bb.w;
    ((float4*)(g_xn + tok*Cv))[t] = o;
}

__global__ void __launch_bounds__(256) ln_kernel(
    const float* __restrict__ x, const float* __restrict__ w,
    const float* __restrict__ b, float* __restrict__ out)
{
    size_t tok = blockIdx.x;
    int t = threadIdx.x;
    float4 v = ((const float4*)(x + tok*Cv))[t];
    float s  = v.x + v.y + v.z + v.w;
    float ss = v.x*v.x + v.y*v.y + v.z*v.z + v.w*v.w;
    block_reduce2(s, ss);
    float mu  = s * (1.f/Cv);
    float inv = rsqrtf(ss * (1.f/Cv) - mu*mu + EPSv);
    float4 W = ((const float4*)w)[t], Bb = ((const float4*)b)[t];
    float4 o;
    o.x = (v.x-mu)*inv*W.x + Bb.x;  o.y = (v.y-mu)*inv*W.y + Bb.y;
    o.z = (v.z-mu)*inv*W.z + Bb.z;  o.w = (v.w-mu)*inv*W.w + Bb.w;
    ((float4*)(out + tok*Cv))[t] = o;
}

// ---------------- token-shift mixing (outputs half: feed GEMMs) -------
__device__ __forceinline__ half4 mix_one_h(float4 cur, float4 prev, float4 m) {
    half4 o;
    o.lo = __floats2half2_rn(cur.x*m.x + prev.x*(1.f - m.x),
                             cur.y*m.y + prev.y*(1.f - m.y));
    o.hi = __floats2half2_rn(cur.z*m.z + prev.z*(1.f - m.z),
                             cur.w*m.w + prev.w*(1.f - m.w));
    return o;
}

__global__ void __launch_bounds__(256) mix4_kernel(
    const float* __restrict__ xn,
    const float* __restrict__ tk, const float* __restrict__ tv,
    const float* __restrict__ tr, const float* __restrict__ tg)
{
    size_t i4 = (size_t)blockIdx.x*256 + threadIdx.x;
    int c4 = (int)(i4 & 255);
    size_t tc = i4 >> 8;
    float4 cur  = ((const float4*)xn)[i4];
    float4 prev = make_float4(0.f,0.f,0.f,0.f);
    if (tc & (Tv-1)) prev = ((const float4*)xn)[i4 - 256];
    ((half4*)h_xk)[i4] = mix_one_h(cur, prev, ((const float4*)tk)[c4]);
    ((half4*)h_xv)[i4] = mix_one_h(cur, prev, ((const float4*)tv)[c4]);
    ((half4*)h_xr)[i4] = mix_one_h(cur, prev, ((const float4*)tr)[c4]);
    ((half4*)h_xg)[i4] = mix_one_h(cur, prev, ((const float4*)tg)[c4]);
}

__global__ void __launch_bounds__(256) mix2_kernel(
    const float* __restrict__ xn,
    const float* __restrict__ tk, const float* __restrict__ tr)
{
    size_t i4 = (size_t)blockIdx.x*256 + threadIdx.x;
    int c4 = (int)(i4 & 255);
    size_t tc = i4 >> 8;
    float4 cur  = ((const float4*)xn)[i4];
    float4 prev = make_float4(0.f,0.f,0.f,0.f);
    if (tc & (Tv-1)) prev = ((const float4*)xn)[i4 - 256];
    ((half4*)h_fxk)[i4] = mix_one_h(cur, prev, ((const float4*)tk)[c4]);
    ((half4*)h_fxr)[i4] = mix_one_h(cur, prev, ((const float4*)tr)[c4]);
}

// ---------------- WKV5 sequential scan ----------------
__global__ void __launch_bounds__(256) wkv5_kernel(
    const float* __restrict__ r, const float* __restrict__ k, const float* __restrict__ v,
    const float* __restrict__ wdec, const float* __restrict__ u, float* __restrict__ y)
{
    int b = blockIdx.x >> 4;
    int h = blockIdx.x & 15;
    int tid = threadIdx.x;
    int j  = tid & 63;
    int ig = tid >> 6;
    __shared__ float rs[64], ks[64], vs[64];
    __shared__ float yred[4][64];
    float S[16], ew[16], uu[16];
    #pragma unroll
    for (int ii = 0; ii < 16; ii++) {
        int i = ig*16 + ii;
        double wv = (double)wdec[h*Nv + i];
        ew[ii] = (float)exp(-exp(wv));
        uu[ii] = u[h*Nv + i];
        S[ii]  = 0.f;
    }
    size_t base = ((size_t)b*Tv)*Cv + (size_t)h*Nv;
    for (int t = 0; t < Tv; t++, base += Cv) {
        if      (tid < 64)  rs[tid]       = r[base + tid];
        else if (tid < 128) ks[tid - 64]  = k[base + tid - 64];
        else if (tid < 192) vs[tid - 128] = v[base + tid - 128];
        __syncthreads();
        float vj = vs[j];
        float yp = 0.f;
        #pragma unroll
        for (int ii = 0; ii < 16; ii++) {
            int i = ig*16 + ii;
            float kv = ks[i] * vj;
            yp    = fmaf(rs[i], fmaf(uu[ii], kv, S[ii]), yp);
            S[ii] = fmaf(ew[ii], S[ii], kv);
        }
        yred[ig][j] = yp;
        __syncthreads();
        if (tid < 64)
            y[base + tid] = yred[0][tid] + yred[1][tid] + yred[2][tid] + yred[3][tid];
        __syncthreads();
    }
}

// ---------------- groupnorm(y/8)*w+b then * silu(g); writes half -------
__global__ void __launch_bounds__(512) gnmul_kernel(
    const float* __restrict__ y, const float* __restrict__ w, const float* __restrict__ b,
    const float* __restrict__ g, __half* __restrict__ out)
{
    size_t tok = blockIdx.x;
    int wg = threadIdx.x >> 5, lane = threadIdx.x & 31;
    size_t base = tok*Cv + (size_t)wg*64;
    float a0 = y[base + lane]      * (1.f/HSDv);
    float a1 = y[base + lane + 32] * (1.f/HSDv);
    float s = a0 + a1, ss = a0*a0 + a1*a1;
    #pragma unroll
    for (int o = 16; o; o >>= 1) {
        s  += __shfl_xor_sync(0xffffffffu, s,  o);
        ss += __shfl_xor_sync(0xffffffffu, ss, o);
    }
    float mu  = s * (1.f/64.f);
    float inv = rsqrtf(ss * (1.f/64.f) - mu*mu + EPSv);
    int c0 = wg*64 + lane;
    out[base + lane]      = __float2half_rn(((a0-mu)*inv*w[c0]      + b[c0])      * g[base + lane]);
    out[base + lane + 32] = __float2half_rn(((a1-mu)*inv*w[c0 + 32] + b[c0 + 32]) * g[base + lane + 32]);
}

// ---------------- final: out = x + sigmoid(sr)*kv ----------------
__global__ void __launch_bounds__(256) final_kernel(float* __restrict__ out) {
    size_t i4 = (size_t)blockIdx.x*256 + threadIdx.x;
    float4 xv = ((const float4*)g_x )[i4];
    float4 sg = ((const float4*)g_sr)[i4];
    float4 kv = ((const float4*)g_kv)[i4];
    float4 o;
    o.x = xv.x + sg.x*kv.x;  o.y = xv.y + sg.y*kv.y;
    o.z = xv.z + sg.z*kv.z;  o.w = xv.w + sg.w*kv.w;
    ((float4*)out)[i4] = o;
}

// ---------------- orchestration ----------------
extern "C" void kernel_launch(void* const* d_in, const int* in_sizes, int n_in,
                              void* d_out, int out_size)
{
    (void)in_sizes; (void)n_in; (void)out_size;
    const float* x     = (const float*)d_in[0];
    const float* ln0w  = (const float*)d_in[1];
    const float* ln0b  = (const float*)d_in[2];
    const float* ln1w  = (const float*)d_in[3];
    const float* ln1b  = (const float*)d_in[4];
    const float* ln2w  = (const float*)d_in[5];
    const float* ln2b  = (const float*)d_in[6];
    const float* tmk   = (const float*)d_in[7];
    const float* tmv   = (const float*)d_in[8];
    const float* tmr   = (const float*)d_in[9];
    const float* tmg   = (const float*)d_in[10];
    const float* decay = (const float*)d_in[11];
    const float* faaaa = (const float*)d_in[12];
    const float* Wr    = (const float*)d_in[13];
    const float* Wk    = (const float*)d_in[14];
    const float* Wv    = (const float*)d_in[15];
    const float* Wg    = (const float*)d_in[16];
    const float* Wo    = (const float*)d_in[17];
    const float* lnxw  = (const float*)d_in[18];
    const float* lnxb  = (const float*)d_in[19];
    const float* ftmk  = (const float*)d_in[20];
    const float* ftmr  = (const float*)d_in[21];
    const float* fWk   = (const float*)d_in[22];
    const float* fWr   = (const float*)d_in[23];
    const float* fWv   = (const float*)d_in[24];

    float *px, *pxn, *pr, *pk, *pv, *pg, *py, *psr, *pkv, *pbig;
    __half *hxk, *hxv, *hxr, *hxg, *hgy, *hfxk, *hfxr, *hbig;
    __half *hwr, *hwk, *hwv, *hwg, *hwo, *hfwk, *hfwr, *hfwv;
    cudaGetSymbolAddress((void**)&px,   g_x);
    cudaGetSymbolAddress((void**)&pxn,  g_xn);
    cudaGetSymbolAddress((void**)&pr,   g_r);
    cudaGetSymbolAddress((void**)&pk,   g_k);
    cudaGetSymbolAddress((void**)&pv,   g_v);
    cudaGetSymbolAddress((void**)&pg,   g_g);
    cudaGetSymbolAddress((void**)&py,   g_y);
    cudaGetSymbolAddress((void**)&psr,  g_sr);
    cudaGetSymbolAddress((void**)&pkv,  g_kv);
    cudaGetSymbolAddress((void**)&pbig, g_big);
    cudaGetSymbolAddress((void**)&hxk,  h_xk);
    cudaGetSymbolAddress((void**)&hxv,  h_xv);
    cudaGetSymbolAddress((void**)&hxr,  h_xr);
    cudaGetSymbolAddress((void**)&hxg,  h_xg);
    cudaGetSymbolAddress((void**)&hgy,  h_gy);
    cudaGetSymbolAddress((void**)&hfxk, h_fxk);
    cudaGetSymbolAddress((void**)&hfxr, h_fxr);
    cudaGetSymbolAddress((void**)&hbig, h_big);
    cudaGetSymbolAddress((void**)&hwr,  h_wr);
    cudaGetSymbolAddress((void**)&hwk,  h_wk);
    cudaGetSymbolAddress((void**)&hwv,  h_wv);
    cudaGetSymbolAddress((void**)&hwg,  h_wg);
    cudaGetSymbolAddress((void**)&hwo,  h_wo);
    cudaGetSymbolAddress((void**)&hfwk, h_fwk);
    cudaGetSymbolAddress((void**)&hfwr, h_fwr);
    cudaGetSymbolAddress((void**)&hfwv, h_fwv);

    cudaFuncSetAttribute(gemm_h<0>, cudaFuncAttributeMaxDynamicSharedMemorySize, GSMEM);
    cudaFuncSetAttribute(gemm_h<1>, cudaFuncAttributeMaxDynamicSharedMemorySize, GSMEM);
    cudaFuncSetAttribute(gemm_h<2>, cudaFuncAttributeMaxDynamicSharedMemorySize, GSMEM);
    cudaFuncSetAttribute(gemm_h<3>, cudaFuncAttributeMaxDynamicSharedMemorySize, GSMEM);
    cudaFuncSetAttribute(gemm_h<4>, cudaFuncAttributeMaxDynamicSharedMemorySize, GSMEM);

    const int nCC4 = Cv*Cv/4, nFF4 = FFNv*Cv/4, nBIG4 = TOK*FFNv/4;
    // weight conversion to fp16 (RN)
    convh_kernel<<<(nCC4+255)/256, 256>>>(Wr,  hwr,  nCC4);
    convh_kernel<<<(nCC4+255)/256, 256>>>(Wk,  hwk,  nCC4);
    convh_kernel<<<(nCC4+255)/256, 256>>>(Wv,  hwv,  nCC4);
    convh_kernel<<<(nCC4+255)/256, 256>>>(Wg,  hwg,  nCC4);
    convh_kernel<<<(nCC4+255)/256, 256>>>(Wo,  hwo,  nCC4);
    convh_kernel<<<(nFF4+255)/256, 256>>>(fWk, hfwk, nFF4);
    convh_kernel<<<(nCC4+255)/256, 256>>>(fWr, hfwr, nCC4);
    convh_kernel<<<(nFF4+255)/256, 256>>>(fWv, hfwv, nFF4);

    dim3 gCC(Cv/BNg,   TOK/BMg);   // (8, 128)
    dim3 gFF(FFNv/BNg, TOK/BMg);   // (28, 128)

    ln0_ln1_kernel<<<TOK, 256>>>(x, ln0w, ln0b, ln1w, ln1b);
    mix4_kernel<<<TOK, 256>>>(pxn, tmk, tmv, tmr, tmg);
    gemm_h<0><<<gCC, 256, GSMEM>>>(hxr, hwr, nullptr, pr, Cv, Cv);
    gemm_h<0><<<gCC, 256, GSMEM>>>(hxk, hwk, nullptr, pk, Cv, Cv);
    gemm_h<0><<<gCC, 256, GSMEM>>>(hxv, hwv, nullptr, pv, Cv, Cv);
    gemm_h<1><<<gCC, 256, GSMEM>>>(hxg, hwg, nullptr, pg, Cv, Cv);
    wkv5_kernel<<<Bv*Hv, 256>>>(pr, pk, pv, decay, faaaa, py);
    gnmul_kernel<<<TOK, 512>>>(py, lnxw, lnxb, pg, hgy);
    gemm_h<4><<<gCC, 256, GSMEM>>>(hgy, hwo, px, px, Cv, Cv);
    ln_kernel<<<TOK, 256>>>(px, ln2w, ln2b, pxn);
    mix2_kernel<<<TOK, 256>>>(pxn, ftmk, ftmr);
    gemm_h<2><<<gFF, 256, GSMEM>>>(hfxk, hfwk, nullptr, pbig, FFNv, Cv);   // relu^2 fp32
    convh_kernel<<<(nBIG4+255)/256, 256>>>(pbig, hbig, nBIG4);
    gemm_h<3><<<gCC, 256, GSMEM>>>(hfxr, hfwr, nullptr, psr, Cv, Cv);      // sigmoid
    gemm_h<0><<<gCC, 256, GSMEM>>>(hbig, hfwv, nullptr, pkv, Cv, FFNv);    // kv
    final_kernel<<<TOK, 256>>>((float*)d_out);
}

// round 7
// speedup vs baseline: 2.8169x; 1.2419x over previous
#include <cuda_runtime.h>
#include <cuda_fp16.h>
#include <mma.h>
#include <cstdint>
#include <cstddef>

using namespace nvcuda;

#define Bv    8
#define Tv    2048
#define Cv    1024
#define Hv    16
#define Nv    64
#define FFNv  3584
#define TOK   (Bv*Tv)            // 16384 tokens
#define HSDv  8.0f
#define EPSv  1e-5f

// ---------------- fp32 scratch ----------------
__device__ float g_x  [(size_t)TOK*Cv];   // residual stream
__device__ float g_xn [(size_t)TOK*Cv];   // layernorm output
__device__ float g_r  [(size_t)TOK*Cv];
__device__ float g_k  [(size_t)TOK*Cv];
__device__ float g_v  [(size_t)TOK*Cv];
__device__ float g_g  [(size_t)TOK*Cv];   // silu(g)
__device__ float g_y  [(size_t)TOK*Cv];   // wkv output
__device__ float g_sr [(size_t)TOK*Cv];   // sigmoid(ffn r)

// ---------------- fp16 scratch (GEMM operands) ----------------
__device__ __half h_xk [(size_t)TOK*Cv];
__device__ __half h_xv [(size_t)TOK*Cv];
__device__ __half h_xr [(size_t)TOK*Cv];
__device__ __half h_xg [(size_t)TOK*Cv];
__device__ __half h_gy [(size_t)TOK*Cv];
__device__ __half h_fxk[(size_t)TOK*Cv];
__device__ __half h_fxr[(size_t)TOK*Cv];
__device__ __half h_big[(size_t)TOK*FFNv];
__device__ __half h_wr [(size_t)Cv*Cv];
__device__ __half h_wk [(size_t)Cv*Cv];
__device__ __half h_wv [(size_t)Cv*Cv];
__device__ __half h_wg [(size_t)Cv*Cv];
__device__ __half h_wo [(size_t)Cv*Cv];
__device__ __half h_fwk[(size_t)FFNv*Cv];
__device__ __half h_fwr[(size_t)Cv*Cv];
__device__ __half h_fwv[(size_t)Cv*FFNv];

struct half4 { __half2 lo, hi; };

// ---------------- helpers ----------------
__device__ __forceinline__ uint32_t smem_u32(const void* p) {
    uint32_t a;
    asm("{ .reg .u64 t; cvta.to.shared.u64 t, %1; cvt.u32.u64 %0, t; }" : "=r"(a) : "l"(p));
    return a;
}
__device__ __forceinline__ void cpa16(uint32_t s, const void* g) {
    asm volatile("cp.async.cg.shared.global [%0], [%1], 16;" :: "r"(s), "l"(g));
}
__device__ __forceinline__ void cpa4(uint32_t s, const void* g) {
    asm volatile("cp.async.ca.shared.global [%0], [%1], 4;" :: "r"(s), "l"(g));
}
#define CPA_COMMIT() asm volatile("cp.async.commit_group;" ::: "memory")
#define CPA_WAIT0()  asm volatile("cp.async.wait_group 0;" ::: "memory")
#define CPA_WAIT1()  asm volatile("cp.async.wait_group 1;" ::: "memory")

// float -> half conversion (weights)
__global__ void __launch_bounds__(256) convh_kernel(const float* __restrict__ src,
                                                    __half* __restrict__ dst, int n4) {
    int i = blockIdx.x*256 + threadIdx.x;
    if (i >= n4) return;
    float4 v = ((const float4*)src)[i];
    half4 o;
    o.lo = __floats2half2_rn(v.x, v.y);
    o.hi = __floats2half2_rn(v.z, v.w);
    ((half4*)dst)[i] = o;
}

// ---------------- FP16 WMMA GEMM:  C[M,N] = A[M,K] @ W[N,K]^T ----------------
// 3-stage cp.async pipeline, one __syncthreads per K-chunk.
// EPI: 0 none, 1 silu, 2 relu^2 (half out), 3 sigmoid, 4 residual add,
//      5 final: out = Cres + Aux*acc
#define BMg 128
#define BNg 128
#define BKg 64
#define BKP 72                              // halves (+16B pad)
#define STG_H ((BMg+BNg)*BKP)               // halves per stage (18432)
#define NSTG 3
#define GSMEM (NSTG*STG_H*2)                // 110592 bytes

__device__ __forceinline__ void load_chunk(const __half* __restrict__ Ab,
                                           const __half* __restrict__ Wb,
                                           int K, int kc, __half* As, __half* Bs, int tid) {
    #pragma unroll
    for (int it = 0; it < 4; it++) {
        int idx = it*256 + tid;          // 0..1023
        int row = idx >> 3, c8 = idx & 7;
        cpa16(smem_u32(As + row*BKP + c8*8), Ab + (size_t)row*K + kc + c8*8);
        cpa16(smem_u32(Bs + row*BKP + c8*8), Wb + (size_t)row*K + kc + c8*8);
    }
}

template<int EPI>
__global__ void __launch_bounds__(256, 2) gemm_h(
    const __half* __restrict__ A, const __half* __restrict__ W,
    const float* __restrict__ Cres, const float* __restrict__ Aux,
    void* __restrict__ Co_, int N, int K)
{
    extern __shared__ __align__(16) __half sm[];

    int tid  = threadIdx.x;
    int warp = tid >> 5;
    int wm = warp >> 1;   // 0..3 -> 32-row strip
    int wn = warp & 1;    // 0..1 -> 64-col strip

    wmma::fragment<wmma::accumulator,16,16,16,float> acc[2][4];
    #pragma unroll
    for (int i = 0; i < 2; i++)
        #pragma unroll
        for (int j = 0; j < 4; j++) wmma::fill_fragment(acc[i][j], 0.f);

    const __half* Ab = A + (size_t)blockIdx.y*BMg*K;
    const __half* Wb = W + (size_t)blockIdx.x*BNg*K;
    const int NC = K / BKg;   // >= 16 always

    load_chunk(Ab, Wb, K, 0,     sm,          sm + BMg*BKP,          tid); CPA_COMMIT();
    load_chunk(Ab, Wb, K, BKg,   sm + STG_H,  sm + STG_H + BMg*BKP,  tid); CPA_COMMIT();

    for (int c = 0; c < NC; c++) {
        if (c + 2 < NC) { CPA_WAIT1(); } else { CPA_WAIT0(); }
        __syncthreads();
        if (c + 2 < NC) {
            int st = (c+2) % NSTG;
            load_chunk(Ab, Wb, K, (c+2)*BKg, sm + st*STG_H, sm + st*STG_H + BMg*BKP, tid);
            CPA_COMMIT();
        }
        const __half* Ac = sm + (c % NSTG)*STG_H;
        const __half* Bc = Ac + BMg*BKP;
        #pragma unroll
        for (int kk = 0; kk < 4; kk++) {
            wmma::fragment<wmma::matrix_a,16,16,16,__half,wmma::row_major> af[2];
            wmma::fragment<wmma::matrix_b,16,16,16,__half,wmma::col_major> bf[4];
            #pragma unroll
            for (int i = 0; i < 2; i++)
                wmma::load_matrix_sync(af[i], Ac + (wm*32 + i*16)*BKP + kk*16, BKP);
            #pragma unroll
            for (int j = 0; j < 4; j++)
                wmma::load_matrix_sync(bf[j], Bc + (wn*64 + j*16)*BKP + kk*16, BKP);
            #pragma unroll
            for (int i = 0; i < 2; i++)
                #pragma unroll
                for (int j = 0; j < 4; j++)
                    wmma::mma_sync(acc[i][j], af[i], bf[j], acc[i][j]);
        }
    }
    __syncthreads();

    #pragma unroll
    for (int i = 0; i < 2; i++)
        #pragma unroll
        for (int j = 0; j < 4; j++) {
            size_t r0 = (size_t)blockIdx.y*BMg + wm*32 + i*16;
            size_t c0 = (size_t)blockIdx.x*BNg + wn*64 + j*16;
            if (EPI == 2) {
                wmma::fragment<wmma::accumulator,16,16,16,__half> hacc;
                #pragma unroll
                for (int e = 0; e < 8; e++) {
                    float v = fmaxf(acc[i][j].x[e], 0.f);
                    hacc.x[e] = __float2half_rn(v*v);
                }
                wmma::store_matrix_sync((__half*)Co_ + r0*N + c0, hacc, N, wmma::mem_row_major);
            } else {
                float* cp = (float*)Co_ + r0*N + c0;
                if (EPI == 4) {
                    wmma::fragment<wmma::accumulator,16,16,16,float> cr;
                    wmma::load_matrix_sync(cr, Cres + r0*N + c0, N, wmma::mem_row_major);
                    #pragma unroll
                    for (int e = 0; e < 8; e++) acc[i][j].x[e] += cr.x[e];
                }
                if (EPI == 5) {
                    wmma::fragment<wmma::accumulator,16,16,16,float> cr, ar;
                    wmma::load_matrix_sync(cr, Cres + r0*N + c0, N, wmma::mem_row_major);
                    wmma::load_matrix_sync(ar, Aux  + r0*N + c0, N, wmma::mem_row_major);
                    #pragma unroll
                    for (int e = 0; e < 8; e++)
                        acc[i][j].x[e] = cr.x[e] + ar.x[e]*acc[i][j].x[e];
                }
                if (EPI == 1) {
                    #pragma unroll
                    for (int e = 0; e < 8; e++) {
                        float v = acc[i][j].x[e];
                        acc[i][j].x[e] = v / (1.f + __expf(-v));
                    }
                }
                if (EPI == 3) {
                    #pragma unroll
                    for (int e = 0; e < 8; e++)
                        acc[i][j].x[e] = 1.f / (1.f + __expf(-acc[i][j].x[e]));
                }
                wmma::store_matrix_sync(cp, acc[i][j], N, wmma::mem_row_major);
            }
        }
}

// ---------------- reductions / LN ----------------
__device__ __forceinline__ void block_reduce2(float& s, float& ss) {
    __shared__ float red[64];
    __syncthreads();
    #pragma unroll
    for (int o = 16; o; o >>= 1) {
        s  += __shfl_xor_sync(0xffffffffu, s,  o);
        ss += __shfl_xor_sync(0xffffffffu, ss, o);
    }
    int lane = threadIdx.x & 31, w = threadIdx.x >> 5;
    if (lane == 0) { red[w] = s; red[32 + w] = ss; }
    __syncthreads();
    if (w == 0) {
        float a = (lane < 8) ? red[lane]      : 0.f;
        float c = (lane < 8) ? red[32 + lane] : 0.f;
        #pragma unroll
        for (int o = 4; o; o >>= 1) {
            a += __shfl_xor_sync(0xffffffffu, a, o);
            c += __shfl_xor_sync(0xffffffffu, c, o);
        }
        if (lane == 0) { red[0] = a; red[32] = c; }
    }
    __syncthreads();
    s = red[0]; ss = red[32];
}

__global__ void __launch_bounds__(256) ln0_ln1_kernel(
    const float* __restrict__ x,
    const float* __restrict__ w0, const float* __restrict__ b0,
    const float* __restrict__ w1, const float* __restrict__ b1)
{
    size_t tok = blockIdx.x;
    int t = threadIdx.x;
    float4 v = ((const float4*)(x + tok*Cv))[t];
    float s  = v.x + v.y + v.z + v.w;
    float ss = v.x*v.x + v.y*v.y + v.z*v.z + v.w*v.w;
    block_reduce2(s, ss);
    float mu  = s * (1.f/Cv);
    float inv = rsqrtf(ss * (1.f/Cv) - mu*mu + EPSv);
    float4 W = ((const float4*)w0)[t], Bb = ((const float4*)b0)[t];
    float4 h;
    h.x = (v.x-mu)*inv*W.x + Bb.x;  h.y = (v.y-mu)*inv*W.y + Bb.y;
    h.z = (v.z-mu)*inv*W.z + Bb.z;  h.w = (v.w-mu)*inv*W.w + Bb.w;
    ((float4*)(g_x + tok*Cv))[t] = h;
    s  = h.x + h.y + h.z + h.w;
    ss = h.x*h.x + h.y*h.y + h.z*h.z + h.w*h.w;
    block_reduce2(s, ss);
    mu  = s * (1.f/Cv);
    inv = rsqrtf(ss * (1.f/Cv) - mu*mu + EPSv);
    W = ((const float4*)w1)[t];  Bb = ((const float4*)b1)[t];
    float4 o;
    o.x = (h.x-mu)*inv*W.x + Bb.x;  o.y = (h.y-mu)*inv*W.y + Bb.y;
    o.z = (h.z-mu)*inv*W.z + Bb.z;  o.w = (h.w-mu)*inv*W.w + Bb.w;
    ((float4*)(g_xn + tok*Cv))[t] = o;
}

__global__ void __launch_bounds__(256) ln_kernel(
    const float* __restrict__ x, const float* __restrict__ w,
    const float* __restrict__ b, float* __restrict__ out)
{
    size_t tok = blockIdx.x;
    int t = threadIdx.x;
    float4 v = ((const float4*)(x + tok*Cv))[t];
    float s  = v.x + v.y + v.z + v.w;
    float ss = v.x*v.x + v.y*v.y + v.z*v.z + v.w*v.w;
    block_reduce2(s, ss);
    float mu  = s * (1.f/Cv);
    float inv = rsqrtf(ss * (1.f/Cv) - mu*mu + EPSv);
    float4 W = ((const float4*)w)[t], Bb = ((const float4*)b)[t];
    float4 o;
    o.x = (v.x-mu)*inv*W.x + Bb.x;  o.y = (v.y-mu)*inv*W.y + Bb.y;
    o.z = (v.z-mu)*inv*W.z + Bb.z;  o.w = (v.w-mu)*inv*W.w + Bb.w;
    ((float4*)(out + tok*Cv))[t] = o;
}

// ---------------- token-shift mixing (outputs half: feed GEMMs) -------
__device__ __forceinline__ half4 mix_one_h(float4 cur, float4 prev, float4 m) {
    half4 o;
    o.lo = __floats2half2_rn(cur.x*m.x + prev.x*(1.f - m.x),
                             cur.y*m.y + prev.y*(1.f - m.y));
    o.hi = __floats2half2_rn(cur.z*m.z + prev.z*(1.f - m.z),
                             cur.w*m.w + prev.w*(1.f - m.w));
    return o;
}

__global__ void __launch_bounds__(256) mix4_kernel(
    const float* __restrict__ xn,
    const float* __restrict__ tk, const float* __restrict__ tv,
    const float* __restrict__ tr, const float* __restrict__ tg)
{
    size_t i4 = (size_t)blockIdx.x*256 + threadIdx.x;
    int c4 = (int)(i4 & 255);
    size_t tc = i4 >> 8;
    float4 cur  = ((const float4*)xn)[i4];
    float4 prev = make_float4(0.f,0.f,0.f,0.f);
    if (tc & (Tv-1)) prev = ((const float4*)xn)[i4 - 256];
    ((half4*)h_xk)[i4] = mix_one_h(cur, prev, ((const float4*)tk)[c4]);
    ((half4*)h_xv)[i4] = mix_one_h(cur, prev, ((const float4*)tv)[c4]);
    ((half4*)h_xr)[i4] = mix_one_h(cur, prev, ((const float4*)tr)[c4]);
    ((half4*)h_xg)[i4] = mix_one_h(cur, prev, ((const float4*)tg)[c4]);
}

__global__ void __launch_bounds__(256) mix2_kernel(
    const float* __restrict__ xn,
    const float* __restrict__ tk, const float* __restrict__ tr)
{
    size_t i4 = (size_t)blockIdx.x*256 + threadIdx.x;
    int c4 = (int)(i4 & 255);
    size_t tc = i4 >> 8;
    float4 cur  = ((const float4*)xn)[i4];
    float4 prev = make_float4(0.f,0.f,0.f,0.f);
    if (tc & (Tv-1)) prev = ((const float4*)xn)[i4 - 256];
    ((half4*)h_fxk)[i4] = mix_one_h(cur, prev, ((const float4*)tk)[c4]);
    ((half4*)h_fxr)[i4] = mix_one_h(cur, prev, ((const float4*)tr)[c4]);
}

// ---------------- WKV5 sequential scan (cp.async prefetch) ----------------
__global__ void __launch_bounds__(256) wkv5_kernel(
    const float* __restrict__ r, const float* __restrict__ k, const float* __restrict__ v,
    const float* __restrict__ wdec, const float* __restrict__ u, float* __restrict__ y)
{
    int b = blockIdx.x >> 4;
    int h = blockIdx.x & 15;
    int tid = threadIdx.x;
    int j  = tid & 63;
    int ig = tid >> 6;
    __shared__ float rkv[2][192];   // [stage][ r:0-63 | k:64-127 | v:128-191 ]
    __shared__ float yred[4][64];
    float S[16], ew[16], uu[16];
    #pragma unroll
    for (int ii = 0; ii < 16; ii++) {
        int i = ig*16 + ii;
        double wv = (double)wdec[h*Nv + i];
        ew[ii] = (float)exp(-exp(wv));
        uu[ii] = u[h*Nv + i];
        S[ii]  = 0.f;
    }
    size_t base = ((size_t)b*Tv)*Cv + (size_t)h*Nv;

    const float* gp = nullptr;
    if (tid < 192) {
        int which = tid >> 6;
        const float* p = (which == 0) ? r : (which == 1) ? k : v;
        gp = p + base + (tid & 63);
    }
    // preload t=0
    if (tid < 192) cpa4(smem_u32(&rkv[0][tid]), gp);
    CPA_COMMIT();
    CPA_WAIT0();
    __syncthreads();

    size_t ybase = base;
    for (int t = 0; t < Tv; t++, ybase += Cv) {
        int cur = t & 1;
        if (t + 1 < Tv && tid < 192) {
            gp += Cv;
            cpa4(smem_u32(&rkv[cur^1][tid]), gp);
            CPA_COMMIT();
        }
        float vj = rkv[cur][128 + j];
        float yp = 0.f;
        #pragma unroll
        for (int ii = 0; ii < 16; ii++) {
            int i = ig*16 + ii;
            float kv = rkv[cur][64 + i] * vj;
            yp    = fmaf(rkv[cur][i], fmaf(uu[ii], kv, S[ii]), yp);
            S[ii] = fmaf(ew[ii], S[ii], kv);
        }
        yred[ig][j] = yp;
        __syncthreads();
        if (tid < 64)
            y[ybase + tid] = yred[0][tid] + yred[1][tid] + yred[2][tid] + yred[3][tid];
        if (t + 1 < Tv) CPA_WAIT0();
        __syncthreads();
    }
}

// ---------------- groupnorm(y/8)*w+b then * silu(g); writes half -------
__global__ void __launch_bounds__(512) gnmul_kernel(
    const float* __restrict__ y, const float* __restrict__ w, const float* __restrict__ b,
    const float* __restrict__ g, __half* __restrict__ out)
{
    size_t tok = blockIdx.x;
    int wg = threadIdx.x >> 5, lane = threadIdx.x & 31;
    size_t base = tok*Cv + (size_t)wg*64;
    float a0 = y[base + lane]      * (1.f/HSDv);
    float a1 = y[base + lane + 32] * (1.f/HSDv);
    float s = a0 + a1, ss = a0*a0 + a1*a1;
    #pragma unroll
    for (int o = 16; o; o >>= 1) {
        s  += __shfl_xor_sync(0xffffffffu, s,  o);
        ss += __shfl_xor_sync(0xffffffffu, ss, o);
    }
    float mu  = s * (1.f/64.f);
    float inv = rsqrtf(ss * (1.f/64.f) - mu*mu + EPSv);
    int c0 = wg*64 + lane;
    out[base + lane]      = __float2half_rn(((a0-mu)*inv*w[c0]      + b[c0])      * g[base + lane]);
    out[base + lane + 32] = __float2half_rn(((a1-mu)*inv*w[c0 + 32] + b[c0 + 32]) * g[base + lane + 32]);
}

// ---------------- orchestration ----------------
extern "C" void kernel_launch(void* const* d_in, const int* in_sizes, int n_in,
                              void* d_out, int out_size)
{
    (void)in_sizes; (void)n_in; (void)out_size;
    const float* x     = (const float*)d_in[0];
    const float* ln0w  = (const float*)d_in[1];
    const float* ln0b  = (const float*)d_in[2];
    const float* ln1w  = (const float*)d_in[3];
    const float* ln1b  = (const float*)d_in[4];
    const float* ln2w  = (const float*)d_in[5];
    const float* ln2b  = (const float*)d_in[6];
    const float* tmk   = (const float*)d_in[7];
    const float* tmv   = (const float*)d_in[8];
    const float* tmr   = (const float*)d_in[9];
    const float* tmg   = (const float*)d_in[10];
    const float* decay = (const float*)d_in[11];
    const float* faaaa = (const float*)d_in[12];
    const float* Wr    = (const float*)d_in[13];
    const float* Wk    = (const float*)d_in[14];
    const float* Wv    = (const float*)d_in[15];
    const float* Wg    = (const float*)d_in[16];
    const float* Wo    = (const float*)d_in[17];
    const float* lnxw  = (const float*)d_in[18];
    const float* lnxb  = (const float*)d_in[19];
    const float* ftmk  = (const float*)d_in[20];
    const float* ftmr  = (const float*)d_in[21];
    const float* fWk   = (const float*)d_in[22];
    const float* fWr   = (const float*)d_in[23];
    const float* fWv   = (const float*)d_in[24];

    float *px, *pxn, *pr, *pk, *pv, *pg, *py, *psr;
    __half *hxk, *hxv, *hxr, *hxg, *hgy, *hfxk, *hfxr, *hbig;
    __half *hwr, *hwk, *hwv, *hwg, *hwo, *hfwk, *hfwr, *hfwv;
    cudaGetSymbolAddress((void**)&px,   g_x);
    cudaGetSymbolAddress((void**)&pxn,  g_xn);
    cudaGetSymbolAddress((void**)&pr,   g_r);
    cudaGetSymbolAddress((void**)&pk,   g_k);
    cudaGetSymbolAddress((void**)&pv,   g_v);
    cudaGetSymbolAddress((void**)&pg,   g_g);
    cudaGetSymbolAddress((void**)&py,   g_y);
    cudaGetSymbolAddress((void**)&psr,  g_sr);
    cudaGetSymbolAddress((void**)&hxk,  h_xk);
    cudaGetSymbolAddress((void**)&hxv,  h_xv);
    cudaGetSymbolAddress((void**)&hxr,  h_xr);
    cudaGetSymbolAddress((void**)&hxg,  h_xg);
    cudaGetSymbolAddress((void**)&hgy,  h_gy);
    cudaGetSymbolAddress((void**)&hfxk, h_fxk);
    cudaGetSymbolAddress((void**)&hfxr, h_fxr);
    cudaGetSymbolAddress((void**)&hbig, h_big);
    cudaGetSymbolAddress((void**)&hwr,  h_wr);
    cudaGetSymbolAddress((void**)&hwk,  h_wk);
    cudaGetSymbolAddress((void**)&hwv,  h_wv);
    cudaGetSymbolAddress((void**)&hwg,  h_wg);
    cudaGetSymbolAddress((void**)&hwo,  h_wo);
    cudaGetSymbolAddress((void**)&hfwk, h_fwk);
    cudaGetSymbolAddress((void**)&hfwr, h_fwr);
    cudaGetSymbolAddress((void**)&hfwv, h_fwv);

    cudaFuncSetAttribute(gemm_h<0>, cudaFuncAttributeMaxDynamicSharedMemorySize, GSMEM);
    cudaFuncSetAttribute(gemm_h<1>, cudaFuncAttributeMaxDynamicSharedMemorySize, GSMEM);
    cudaFuncSetAttribute(gemm_h<2>, cudaFuncAttributeMaxDynamicSharedMemorySize, GSMEM);
    cudaFuncSetAttribute(gemm_h<3>, cudaFuncAttributeMaxDynamicSharedMemorySize, GSMEM);
    cudaFuncSetAttribute(gemm_h<4>, cudaFuncAttributeMaxDynamicSharedMemorySize, GSMEM);
    cudaFuncSetAttribute(gemm_h<5>, cudaFuncAttributeMaxDynamicSharedMemorySize, GSMEM);

    const int nCC4 = Cv*Cv/4, nFF4 = FFNv*Cv/4;
    convh_kernel<<<(nCC4+255)/256, 256>>>(Wr,  hwr,  nCC4);
    convh_kernel<<<(nCC4+255)/256, 256>>>(Wk,  hwk,  nCC4);
    convh_kernel<<<(nCC4+255)/256, 256>>>(Wv,  hwv,  nCC4);
    convh_kernel<<<(nCC4+255)/256, 256>>>(Wg,  hwg,  nCC4);
    convh_kernel<<<(nCC4+255)/256, 256>>>(Wo,  hwo,  nCC4);
    convh_kernel<<<(nFF4+255)/256, 256>>>(fWk, hfwk, nFF4);
    convh_kernel<<<(nCC4+255)/256, 256>>>(fWr, hfwr, nCC4);
    convh_kernel<<<(nFF4+255)/256, 256>>>(fWv, hfwv, nFF4);

    dim3 gCC(Cv/BNg,   TOK/BMg);   // (8, 128)
    dim3 gFF(FFNv/BNg, TOK/BMg);   // (28, 128)

    ln0_ln1_kernel<<<TOK, 256>>>(x, ln0w, ln0b, ln1w, ln1b);
    mix4_kernel<<<TOK, 256>>>(pxn, tmk, tmv, tmr, tmg);
    gemm_h<0><<<gCC, 256, GSMEM>>>(hxr, hwr, nullptr, nullptr, pr, Cv, Cv);
    gemm_h<0><<<gCC, 256, GSMEM>>>(hxk, hwk, nullptr, nullptr, pk, Cv, Cv);
    gemm_h<0><<<gCC, 256, GSMEM>>>(hxv, hwv, nullptr, nullptr, pv, Cv, Cv);
    gemm_h<1><<<gCC, 256, GSMEM>>>(hxg, hwg, nullptr, nullptr, pg, Cv, Cv);
    wkv5_kernel<<<Bv*Hv, 256>>>(pr, pk, pv, decay, faaaa, py);
    gnmul_kernel<<<TOK, 512>>>(py, lnxw, lnxb, pg, hgy);
    gemm_h<4><<<gCC, 256, GSMEM>>>(hgy, hwo, px, nullptr, px, Cv, Cv);
    ln_kernel<<<TOK, 256>>>(px, ln2w, ln2b, pxn);
    mix2_kernel<<<TOK, 256>>>(pxn, ftmk, ftmr);
    gemm_h<2><<<gFF, 256, GSMEM>>>(hfxk, hfwk, nullptr, nullptr, hbig, FFNv, Cv);  // relu^2 -> half
    gemm_h<3><<<gCC, 256, GSMEM>>>(hfxr, hfwr, nullptr, nullptr, psr, Cv, Cv);     // sigmoid
    gemm_h<5><<<gCC, 256, GSMEM>>>(hbig, hfwv, px, psr, d_out, Cv, FFNv);          // out = x + sr*kv
}